// round 4
// baseline (speedup 1.0000x reference)
#include <cuda_runtime.h>
#include <cuda_bf16.h>

#define NN 500000
#define NE 16000000

// Scratch (__device__ globals: zero-initialized at load; out_pass re-zeros
// accumulators at the end of every call, so each call starts from zero).
__device__ float2 g_acc1[NN];   // {sum(in_feat[src]*e_feat), deg}
__device__ float  g_s[NN];      // s = h1 · W2_neigh  (pass2 gather target)
__device__ float  g_t[NN];      // t = h1 · W2_self
__device__ float  g_agg2[NN];   // sum(s[src]*e_feat)

#define EDGE_BLOCKS 1184   // 148 SMs * 8 resident blocks
#define TB 256

// ---------------------------------------------------------------------------
// Pass 1: layer-1 scalar edge aggregation. Grid-stride, 4 edges per step.
__global__ void __launch_bounds__(256) edge_pass1(
    const float* __restrict__ in_feat,
    const float* __restrict__ e_feat,
    const int*   __restrict__ src,
    const int*   __restrict__ dst)
{
    const long stride = (long)gridDim.x * blockDim.x * 4;
    for (long base = ((long)blockIdx.x * blockDim.x + threadIdx.x) * 4;
         base < NE; base += stride) {
        // NE % 4 == 0 and base is a multiple of 4, so the vector path is exact.
        int4   s4 = *reinterpret_cast<const int4*>(src + base);
        int4   d4 = *reinterpret_cast<const int4*>(dst + base);
        float4 e4 = *reinterpret_cast<const float4*>(e_feat + base);
        atomicAdd(&g_acc1[d4.x], make_float2(__ldg(in_feat + s4.x) * e4.x, 1.f));
        atomicAdd(&g_acc1[d4.y], make_float2(__ldg(in_feat + s4.y) * e4.y, 1.f));
        atomicAdd(&g_acc1[d4.z], make_float2(__ldg(in_feat + s4.z) * e4.z, 1.f));
        atomicAdd(&g_acc1[d4.w], make_float2(__ldg(in_feat + s4.w) * e4.w, 1.f));
    }
}

// ---------------------------------------------------------------------------
// Node pass: hn1 = agg1/deg; h1 = sigmoid(x*W1s + hn1*W1n + b1);
// s = h1·W2_neigh, t = h1·W2_self.  (PDL secondary: waits on pass1.)
__global__ void __launch_bounds__(256) node_pass(
    const float* __restrict__ in_feat,
    const float* __restrict__ W1_self,
    const float* __restrict__ W1_neigh,
    const float* __restrict__ b1,
    const float* __restrict__ W2_self,
    const float* __restrict__ W2_neigh)
{
    cudaGridDependencySynchronize();
    int n = blockIdx.x * blockDim.x + threadIdx.x;
    if (n >= NN) return;
    float2 acc = g_acc1[n];
    float hn = (acc.y > 0.f) ? acc.x / acc.y : 0.f;
    float x  = in_feat[n];
    float s = 0.f, t = 0.f;
#pragma unroll
    for (int j = 0; j < 10; ++j) {
        float z = fmaf(x, __ldg(W1_self + j),
                  fmaf(hn, __ldg(W1_neigh + j), __ldg(b1 + j)));
        float h1 = __fdividef(1.f, 1.f + __expf(-z));
        s = fmaf(h1, __ldg(W2_neigh + j), s);
        t = fmaf(h1, __ldg(W2_self + j), t);
    }
    g_s[n] = s;
    g_t[n] = t;
}

// ---------------------------------------------------------------------------
// Pass 2: layer-2 scalar edge aggregation of s[src]*e_feat. Grid-stride.
__global__ void __launch_bounds__(256) edge_pass2(
    const float* __restrict__ e_feat,
    const int*   __restrict__ src,
    const int*   __restrict__ dst)
{
    cudaGridDependencySynchronize();
    const long stride = (long)gridDim.x * blockDim.x * 4;
    for (long base = ((long)blockIdx.x * blockDim.x + threadIdx.x) * 4;
         base < NE; base += stride) {
        int4   s4 = *reinterpret_cast<const int4*>(src + base);
        int4   d4 = *reinterpret_cast<const int4*>(dst + base);
        float4 e4 = *reinterpret_cast<const float4*>(e_feat + base);
        atomicAdd(&g_agg2[d4.x], __ldg(g_s + s4.x) * e4.x);
        atomicAdd(&g_agg2[d4.y], __ldg(g_s + s4.y) * e4.y);
        atomicAdd(&g_agg2[d4.z], __ldg(g_s + s4.z) * e4.z);
        atomicAdd(&g_agg2[d4.w], __ldg(g_s + s4.w) * e4.w);
    }
}

// ---------------------------------------------------------------------------
// Output + re-zero accumulators for the next call.
__global__ void __launch_bounds__(256) out_pass(
    const float* __restrict__ b2, float* __restrict__ out)
{
    cudaGridDependencySynchronize();
    int n = blockIdx.x * blockDim.x + threadIdx.x;
    if (n >= NN) return;
    float deg = g_acc1[n].y;
    float a2  = g_agg2[n];
    float hn2 = (deg > 0.f) ? a2 / deg : 0.f;
    out[n] = g_t[n] + hn2 + __ldg(b2);
    g_acc1[n] = make_float2(0.f, 0.f);
    g_agg2[n] = 0.f;
}

extern "C" void kernel_launch(void* const* d_in, const int* in_sizes, int n_in,
                              void* d_out, int out_size)
{
    const float* in_feat  = (const float*)d_in[0];
    const float* e_feat   = (const float*)d_in[1];
    const int*   src      = (const int*)  d_in[2];
    const int*   dst      = (const int*)  d_in[3];
    const float* W1_self  = (const float*)d_in[4];
    const float* W1_neigh = (const float*)d_in[5];
    const float* b1       = (const float*)d_in[6];
    const float* W2_self  = (const float*)d_in[7];
    const float* W2_neigh = (const float*)d_in[8];
    const float* b2       = (const float*)d_in[9];
    float* out = (float*)d_out;

    int node_blocks = (NN + TB - 1) / TB;

    // Primary: plain launch.
    edge_pass1<<<EDGE_BLOCKS, TB>>>(in_feat, e_feat, src, dst);

    // Secondaries: PDL (programmatic stream serialization) — each begins with
    // cudaGridDependencySynchronize() before touching the producer's output.
    cudaLaunchAttribute attr[1];
    attr[0].id = cudaLaunchAttributeProgrammaticStreamSerialization;
    attr[0].val.programmaticStreamSerializationAllowed = 1;

    cudaLaunchConfig_t cfg = {};
    cfg.blockDim = dim3(TB, 1, 1);
    cfg.stream = 0;
    cfg.attrs = attr;
    cfg.numAttrs = 1;

    cfg.gridDim = dim3(node_blocks, 1, 1);
    cudaLaunchKernelEx(&cfg, node_pass, in_feat, W1_self, W1_neigh, b1,
                       W2_self, W2_neigh);

    cfg.gridDim = dim3(EDGE_BLOCKS, 1, 1);
    cudaLaunchKernelEx(&cfg, edge_pass2, e_feat, src, dst);

    cfg.gridDim = dim3(node_blocks, 1, 1);
    cudaLaunchKernelEx(&cfg, out_pass, b2, out);
}

// round 5
// speedup vs baseline: 1.0589x; 1.0589x over previous
#include <cuda_runtime.h>
#include <cuda_bf16.h>

#define NN 500000
#define NE 16000000

// Scratch (__device__ globals: zero-initialized at load; out_pass re-zeros
// accumulators at the end of every call, so each call starts from zero).
__device__ float2 g_acc1[NN];   // {sum(in_feat[src]*e_feat), deg}
__device__ float  g_s[NN];      // s = h1 · W2_neigh  (pass2 gather target)
__device__ float  g_t[NN];      // t = h1 · W2_self
__device__ float  g_agg2[NN];   // sum(s[src]*e_feat)

#define TB 256

// ---------------------------------------------------------------------------
// Pass 1: layer-1 scalar edge aggregation. 4 edges/thread, one shot (R3 config).
__global__ void __launch_bounds__(256) edge_pass1(
    const float* __restrict__ in_feat,
    const float* __restrict__ e_feat,
    const int*   __restrict__ src,
    const int*   __restrict__ dst)
{
    long base = ((long)blockIdx.x * blockDim.x + threadIdx.x) * 4;
    if (base + 3 < NE) {
        int4   s4 = *reinterpret_cast<const int4*>(src + base);
        int4   d4 = *reinterpret_cast<const int4*>(dst + base);
        float4 e4 = *reinterpret_cast<const float4*>(e_feat + base);
        atomicAdd(&g_acc1[d4.x], make_float2(__ldg(in_feat + s4.x) * e4.x, 1.f));
        atomicAdd(&g_acc1[d4.y], make_float2(__ldg(in_feat + s4.y) * e4.y, 1.f));
        atomicAdd(&g_acc1[d4.z], make_float2(__ldg(in_feat + s4.z) * e4.z, 1.f));
        atomicAdd(&g_acc1[d4.w], make_float2(__ldg(in_feat + s4.w) * e4.w, 1.f));
    } else {
        for (long e = base; e < NE; ++e)
            atomicAdd(&g_acc1[dst[e]],
                      make_float2(__ldg(in_feat + src[e]) * e_feat[e], 1.f));
    }
}

// ---------------------------------------------------------------------------
// Node pass: hn1 = agg1/deg; h1 = sigmoid(x*W1s + hn1*W1n + b1);
// s = h1·W2_neigh, t = h1·W2_self.  (PDL secondary.)
__global__ void __launch_bounds__(256) node_pass(
    const float* __restrict__ in_feat,
    const float* __restrict__ W1_self,
    const float* __restrict__ W1_neigh,
    const float* __restrict__ b1,
    const float* __restrict__ W2_self,
    const float* __restrict__ W2_neigh)
{
    cudaGridDependencySynchronize();
    int n = blockIdx.x * blockDim.x + threadIdx.x;
    if (n >= NN) return;
    float2 acc = g_acc1[n];
    float hn = (acc.y > 0.f) ? acc.x / acc.y : 0.f;
    float x  = in_feat[n];
    float s = 0.f, t = 0.f;
#pragma unroll
    for (int j = 0; j < 10; ++j) {
        float z = fmaf(x, __ldg(W1_self + j),
                  fmaf(hn, __ldg(W1_neigh + j), __ldg(b1 + j)));
        float h1 = __fdividef(1.f, 1.f + __expf(-z));
        s = fmaf(h1, __ldg(W2_neigh + j), s);
        t = fmaf(h1, __ldg(W2_self + j), t);
    }
    g_s[n] = s;
    g_t[n] = t;
}

// ---------------------------------------------------------------------------
// Pass 2: layer-2 scalar edge aggregation of s[src]*e_feat. (PDL secondary.)
__global__ void __launch_bounds__(256) edge_pass2(
    const float* __restrict__ e_feat,
    const int*   __restrict__ src,
    const int*   __restrict__ dst)
{
    cudaGridDependencySynchronize();
    long base = ((long)blockIdx.x * blockDim.x + threadIdx.x) * 4;
    if (base + 3 < NE) {
        int4   s4 = *reinterpret_cast<const int4*>(src + base);
        int4   d4 = *reinterpret_cast<const int4*>(dst + base);
        float4 e4 = *reinterpret_cast<const float4*>(e_feat + base);
        atomicAdd(&g_agg2[d4.x], __ldg(g_s + s4.x) * e4.x);
        atomicAdd(&g_agg2[d4.y], __ldg(g_s + s4.y) * e4.y);
        atomicAdd(&g_agg2[d4.z], __ldg(g_s + s4.z) * e4.z);
        atomicAdd(&g_agg2[d4.w], __ldg(g_s + s4.w) * e4.w);
    } else {
        for (long e = base; e < NE; ++e)
            atomicAdd(&g_agg2[dst[e]], __ldg(g_s + src[e]) * e_feat[e]);
    }
}

// ---------------------------------------------------------------------------
// Output + re-zero accumulators for the next call. (PDL secondary.)
__global__ void __launch_bounds__(256) out_pass(
    const float* __restrict__ b2, float* __restrict__ out)
{
    cudaGridDependencySynchronize();
    int n = blockIdx.x * blockDim.x + threadIdx.x;
    if (n >= NN) return;
    float deg = g_acc1[n].y;
    float a2  = g_agg2[n];
    float hn2 = (deg > 0.f) ? a2 / deg : 0.f;
    out[n] = g_t[n] + hn2 + __ldg(b2);
    g_acc1[n] = make_float2(0.f, 0.f);
    g_agg2[n] = 0.f;
}

extern "C" void kernel_launch(void* const* d_in, const int* in_sizes, int n_in,
                              void* d_out, int out_size)
{
    const float* in_feat  = (const float*)d_in[0];
    const float* e_feat   = (const float*)d_in[1];
    const int*   src      = (const int*)  d_in[2];
    const int*   dst      = (const int*)  d_in[3];
    const float* W1_self  = (const float*)d_in[4];
    const float* W1_neigh = (const float*)d_in[5];
    const float* b1       = (const float*)d_in[6];
    const float* W2_self  = (const float*)d_in[7];
    const float* W2_neigh = (const float*)d_in[8];
    const float* b2       = (const float*)d_in[9];
    float* out = (float*)d_out;

    int node_blocks = (NN + TB - 1) / TB;
    int edge_threads = (NE + 3) / 4;
    int edge_blocks = (edge_threads + TB - 1) / TB;

    // Primary: plain launch.
    edge_pass1<<<edge_blocks, TB>>>(in_feat, e_feat, src, dst);

    // Secondaries: PDL (programmatic stream serialization); each starts with
    // cudaGridDependencySynchronize() before touching producer output.
    cudaLaunchAttribute attr[1];
    attr[0].id = cudaLaunchAttributeProgrammaticStreamSerialization;
    attr[0].val.programmaticStreamSerializationAllowed = 1;

    cudaLaunchConfig_t cfg = {};
    cfg.blockDim = dim3(TB, 1, 1);
    cfg.stream = 0;
    cfg.attrs = attr;
    cfg.numAttrs = 1;

    cfg.gridDim = dim3(node_blocks, 1, 1);
    cudaLaunchKernelEx(&cfg, node_pass, in_feat, W1_self, W1_neigh, b1,
                       W2_self, W2_neigh);

    cfg.gridDim = dim3(edge_blocks, 1, 1);
    cudaLaunchKernelEx(&cfg, edge_pass2, e_feat, src, dst);

    cfg.gridDim = dim3(node_blocks, 1, 1);
    cudaLaunchKernelEx(&cfg, out_pass, b2, out);
}